// round 8
// baseline (speedup 1.0000x reference)
#include <cuda_runtime.h>
#include <cstdint>
#include <cstdio>

#define S_LEN 1024
#define B_SZ  128
#define D_IN  256
#define H_SZ  512
#define C_OUT 128

// ---------------- device scratch ----------------
__device__ float g_T[(size_t)S_LEN * B_SZ * H_SZ];   // x@W_tau_x + b_tau_lin + b_tau
__device__ float g_G[(size_t)S_LEN * B_SZ * H_SZ];   // x@W_in + b_in
__device__ float g_buf[16 * 512 * 8];                // final mem: [cluster][h][b]
__device__ int   g_cnt;

__global__ void init_kernel() { g_cnt = 0; }

// ---------------- Phase 1: fused precompute GEMM (scalar fp32, R2-proven) ----------------
__global__ __launch_bounds__(256, 2) void phase1_kernel(
    const float* __restrict__ x, const float* __restrict__ Win,
    const float* __restrict__ bin, const float* __restrict__ Wtau,
    const float* __restrict__ btl, const float* __restrict__ bt)
{
    __shared__ float As[2][16][128];   // As[k][m]
    __shared__ float Bs[2][16][128];   // Bs[k][n]

    const int tid = threadIdx.x;
    const int m0 = blockIdx.y * 128;
    const int n0 = blockIdx.x * 128;
    const bool isG = (n0 < 512);
    const float* __restrict__ Bp = isG ? (Win + n0) : (Wtau + (n0 - 512));

    const int q0 = tid, q1 = tid + 256;
    const int ar0 = q0 >> 2, ak0 = (q0 & 3) * 4;
    const int ar1 = q1 >> 2, ak1 = (q1 & 3) * 4;
    const int m_0 = m0 + ar0, m_1 = m0 + ar1;
    const float* ap0 = x + ((size_t)(m_0 & 127) * 1024 + (m_0 >> 7)) * 256 + ak0;
    const float* ap1 = x + ((size_t)(m_1 & 127) * 1024 + (m_1 >> 7)) * 256 + ak1;
    const int bk0 = q0 >> 5, bn0 = (q0 & 31) * 4;
    const int bk1 = q1 >> 5, bn1 = (q1 & 31) * 4;

    const int tx = tid & 15, ty = tid >> 4;
    const int c0 = tx * 4, c1 = tx * 4 + 64;
    const int r0 = ty * 4, r1 = ty * 4 + 64;

    float acc[8][8];
#pragma unroll
    for (int i = 0; i < 8; i++)
#pragma unroll
        for (int j = 0; j < 8; j++) acc[i][j] = 0.f;

    float4 pa0 = *(const float4*)(ap0);
    float4 pa1 = *(const float4*)(ap1);
    float4 pb0 = *(const float4*)(Bp + (size_t)bk0 * 512 + bn0);
    float4 pb1 = *(const float4*)(Bp + (size_t)bk1 * 512 + bn1);

    As[0][ak0 + 0][ar0] = pa0.x; As[0][ak0 + 1][ar0] = pa0.y;
    As[0][ak0 + 2][ar0] = pa0.z; As[0][ak0 + 3][ar0] = pa0.w;
    As[0][ak1 + 0][ar1] = pa1.x; As[0][ak1 + 1][ar1] = pa1.y;
    As[0][ak1 + 2][ar1] = pa1.z; As[0][ak1 + 3][ar1] = pa1.w;
    *(float4*)&Bs[0][bk0][bn0] = pb0;
    *(float4*)&Bs[0][bk1][bn1] = pb1;
    __syncthreads();

    int p = 0;
    for (int kt = 0; kt < 16; kt++) {
        if (kt < 15) {
            const int kc = (kt + 1) * 16;
            pa0 = *(const float4*)(ap0 + kc);
            pa1 = *(const float4*)(ap1 + kc);
            pb0 = *(const float4*)(Bp + (size_t)(kc + bk0) * 512 + bn0);
            pb1 = *(const float4*)(Bp + (size_t)(kc + bk1) * 512 + bn1);
        }
#pragma unroll
        for (int k = 0; k < 16; k++) {
            float4 a0 = *(const float4*)&As[p][k][r0];
            float4 a1 = *(const float4*)&As[p][k][r1];
            float4 b0 = *(const float4*)&Bs[p][k][c0];
            float4 b1 = *(const float4*)&Bs[p][k][c1];
            float av[8] = {a0.x, a0.y, a0.z, a0.w, a1.x, a1.y, a1.z, a1.w};
            float bv[8] = {b0.x, b0.y, b0.z, b0.w, b1.x, b1.y, b1.z, b1.w};
#pragma unroll
            for (int i = 0; i < 8; i++)
#pragma unroll
                for (int j = 0; j < 8; j++)
                    acc[i][j] = fmaf(av[i], bv[j], acc[i][j]);
        }
        if (kt < 15) {
            const int np = p ^ 1;
            As[np][ak0 + 0][ar0] = pa0.x; As[np][ak0 + 1][ar0] = pa0.y;
            As[np][ak0 + 2][ar0] = pa0.z; As[np][ak0 + 3][ar0] = pa0.w;
            As[np][ak1 + 0][ar1] = pa1.x; As[np][ak1 + 1][ar1] = pa1.y;
            As[np][ak1 + 2][ar1] = pa1.z; As[np][ak1 + 3][ar1] = pa1.w;
            *(float4*)&Bs[np][bk0][bn0] = pb0;
            *(float4*)&Bs[np][bk1][bn1] = pb1;
        }
        __syncthreads();
        p ^= 1;
    }

    float* dst = isG ? g_G : g_T;
    const int coloff = isG ? n0 : (n0 - 512);
    float bias[8];
#pragma unroll
    for (int j = 0; j < 8; j++) {
        const int ncol = (j < 4) ? (c0 + j) : (c1 + j - 4);
        const int gb = coloff + ncol;
        bias[j] = isG ? bin[gb] : (btl[gb] + bt[gb]);
    }
#pragma unroll
    for (int i = 0; i < 8; i++) {
        const int mrow = m0 + ((i < 4) ? (r0 + i) : (r1 + i - 4));
        float4 o0 = make_float4(acc[i][0] + bias[0], acc[i][1] + bias[1],
                                acc[i][2] + bias[2], acc[i][3] + bias[3]);
        float4 o1 = make_float4(acc[i][4] + bias[4], acc[i][5] + bias[5],
                                acc[i][6] + bias[6], acc[i][7] + bias[7]);
        *(float4*)(dst + (size_t)mrow * 512 + coloff + c0) = o0;
        *(float4*)(dst + (size_t)mrow * 512 + coloff + c1) = o1;
    }
}

// ---------------- Phase 2: persistent recurrent kernel (remote-read exchange) ----------------
__device__ __forceinline__ unsigned smem_u32_addr(const void* p) {
    unsigned a;
    asm("{ .reg .u64 t; cvta.to.shared.u64 t, %1; cvt.u32.u64 %0, t; }"
        : "=r"(a) : "l"(p));
    return a;
}

__device__ __forceinline__ float4 lds_cluster_v4(unsigned addr) {
    float4 v;
    asm volatile("ld.shared::cluster.v4.f32 {%0,%1,%2,%3}, [%4];"
                 : "=f"(v.x), "=f"(v.y), "=f"(v.z), "=f"(v.w) : "r"(addr));
    return v;
}

#define CLUSTER_BARRIER() \
    asm volatile("barrier.cluster.arrive.aligned;\n\tbarrier.cluster.wait.aligned;" ::: "memory")

// smem layout offsets (bytes)
#define WM_BYTES   (512 * 64 * 4)              // 131072
#define MEMB_OFF   WM_BYTES                    // [2][64][8] floats (own slice only)
#define MEMB_BYTES (2 * 64 * 8 * 4)            // 4096
#define PART_OFF   (MEMB_OFF + MEMB_BYTES)     // [16][512] floats
#define PART_BYTES (16 * 512 * 4)              // 32768
#define MBAR_OFF   (PART_OFF + PART_BYTES)     // [2][8] x u64
#define REC_SMEM   (MBAR_OFF + 128)

__global__ void __cluster_dims__(8, 1, 1) __launch_bounds__(512, 1)
recurrent_kernel(const float* __restrict__ Wtau)
{
    extern __shared__ float sm[];
    float* Wm   = sm;                          // [512][64]   128 KB (k-major, 64 cols)
    float* memB = sm + 512 * 64;               // [2][64][8]    4 KB (own slice, h-major)
    float* part = memB + 2 * 64 * 8;           // [16][512]    32 KB

    const int tid  = threadIdx.x;
    const int lane = tid & 31;
    const int w    = tid >> 5;                 // 0..15
    const int r    = blockIdx.x & 7;           // cluster rank -> column slice
    const int cl   = blockIdx.x >> 3;          // cluster index -> 8 batch rows
    const int b0   = cl * 8;

    // Load W_tau_m slice: rows 256..767, cols r*64..r*64+63
    for (int idx = tid; idx < 512 * 64; idx += 512) {
        const int k = idx >> 6, c = idx & 63;
        Wm[idx] = Wtau[(size_t)(256 + k) * 512 + r * 64 + c];
    }
    // Zero both own-slice mem buffers (t=0 input)
    for (int idx = tid; idx < 2 * 64 * 8; idx += 512) memB[idx] = 0.f;

    const unsigned sbase = smem_u32_addr(sm);
    const unsigned mbar_base = sbase + MBAR_OFF;
    if (tid < 16) {
        asm volatile("mbarrier.init.shared.b64 [%0], %1;"
                     :: "r"(mbar_base + tid * 8), "r"(1) : "memory");
    }
    // hoisted mapa: smem base of every cluster CTA
    unsigned pbase[8];
#pragma unroll
    for (int q = 0; q < 8; q++)
        asm("mapa.shared::cluster.u32 %0, %1, %2;" : "=r"(pbase[q]) : "r"(sbase), "r"(q));

    CLUSTER_BARRIER();   // mbar init + memB zero visible cluster-wide

    // elementwise role: one cell (bb, ce) per thread
    const int ce = tid & 63;
    const int bb = tid >> 6;                   // batch 0..7
    const int gh = r * 64 + ce;                // global hidden col
    const int k0 = w * 32;                     // warp K-split (32 k's per warp)
    const int src = w >> 1;                    // source rank whose slice holds this k-range
    const bool remote = (src != r);
    // remote base address of my k-range within source's slice (bytes):
    // source local layout: memB[buf][k_local][b], k_local = k - src*64
    const unsigned rm_base = pbase[src] + MEMB_OFF + (unsigned)((w & 1) * 1024);
    const unsigned my_mbar_b0 = mbar_base + (unsigned)(src * 8);
    const unsigned my_mbar_b1 = mbar_base + (unsigned)(64 + src * 8);

    float cnt = 0.f;

    for (int t = 0; t < S_LEN; t++) {
        const int cb = t & 1, nb = cb ^ 1;

        // prefetch T/G (consumed after GEMM)
        const size_t row = ((size_t)t * B_SZ + b0 + bb) * H_SZ + gh;
        const float Tv = g_T[row], Gv = g_G[row];

        // ---- per-warp wait: my source's slice(t-1) must be published ----
        if (t > 0 && remote) {
            const unsigned ph = (unsigned)(((t - 1) >> 1) & 1);
            const unsigned mb = cb ? my_mbar_b1 : my_mbar_b0;
            asm volatile(
                "{\n\t"
                ".reg .pred P;\n\t"
                "W_%=:\n\t"
                "mbarrier.try_wait.parity.acquire.cluster.shared::cta.b64 P, [%0], %1, 0x989680;\n\t"
                "@P bra D_%=;\n\t"
                "bra W_%=;\n\t"
                "D_%=:\n\t"
                "}"
                :: "r"(mb), "r"(ph) : "memory");
        }

        // ---- GEMM: out[b][c] = sum_k mem[k][b] * Wm[k][c], mem read from source CTA ----
        float acc_a[8], acc_b[8];
#pragma unroll
        for (int b = 0; b < 8; b++) { acc_a[b] = 0.f; acc_b[b] = 0.f; }

        const unsigned mp_r = rm_base + (unsigned)(cb * 2048);
        const float* wp = Wm + k0 * 64;

        // double-buffered groups of 2 k's (16 floats = 64B per group), 16 groups
        float rb[2][16];
        {
            float4 a = lds_cluster_v4(mp_r);
            float4 b4 = lds_cluster_v4(mp_r + 16);
            float4 c = lds_cluster_v4(mp_r + 32);
            float4 d = lds_cluster_v4(mp_r + 48);
            rb[0][0]=a.x; rb[0][1]=a.y; rb[0][2]=a.z; rb[0][3]=a.w;
            rb[0][4]=b4.x; rb[0][5]=b4.y; rb[0][6]=b4.z; rb[0][7]=b4.w;
            rb[0][8]=c.x; rb[0][9]=c.y; rb[0][10]=c.z; rb[0][11]=c.w;
            rb[0][12]=d.x; rb[0][13]=d.y; rb[0][14]=d.z; rb[0][15]=d.w;
        }
#pragma unroll
        for (int g = 0; g < 16; g++) {
            if (g < 15) {
                const unsigned ga = mp_r + (unsigned)((g + 1) * 64);
                float4 a = lds_cluster_v4(ga);
                float4 b4 = lds_cluster_v4(ga + 16);
                float4 c = lds_cluster_v4(ga + 32);
                float4 d = lds_cluster_v4(ga + 48);
                float* dst = rb[(g + 1) & 1];
                dst[0]=a.x; dst[1]=a.y; dst[2]=a.z; dst[3]=a.w;
                dst[4]=b4.x; dst[5]=b4.y; dst[6]=b4.z; dst[7]=b4.w;
                dst[8]=c.x; dst[9]=c.y; dst[10]=c.z; dst[11]=c.w;
                dst[12]=d.x; dst[13]=d.y; dst[14]=d.z; dst[15]=d.w;
            }
            const float* rm = rb[g & 1];
#pragma unroll
            for (int j = 0; j < 2; j++) {
                const int k = 2 * g + j;
                const float2 wv = *(const float2*)(wp + k * 64 + 2 * lane);
#pragma unroll
                for (int b = 0; b < 8; b++) {
                    acc_a[b] = fmaf(rm[j * 8 + b], wv.x, acc_a[b]);
                    acc_b[b] = fmaf(rm[j * 8 + b], wv.y, acc_b[b]);
                }
            }
        }
        // warp partials: part[w][b*64 + 2*lane .. +1]
#pragma unroll
        for (int b = 0; b < 8; b++) {
            *(float2*)&part[w * 512 + b * 64 + 2 * lane] = make_float2(acc_a[b], acc_b[b]);
        }
        __syncthreads();

        // ---- reduce 16 warp partials + elementwise update for cell (bb, ce) ----
        float s = 0.f;
#pragma unroll
        for (int ww = 0; ww < 16; ww++)
            s += part[ww * 512 + bb * 64 + ce];
        const float l = Tv + s;
        float beta = 1.f / (1.f + expf(-l));
        beta = fminf(fmaxf(beta, 0.01f), 0.99f);
        const float mo = memB[cb * 512 + ce * 8 + bb];
        float mn = fmaf(beta, mo, Gv);
        const float sp = ((mn - 1.0f) > 0.0f) ? 1.f : 0.f;
        mn -= sp;
        cnt += sp;

        if (t < S_LEN - 1) {
            // write updated own-slice value into local next buffer
            memB[nb * 512 + ce * 8 + bb] = mn;
            __syncthreads();   // slice complete; all this-step reads of memB[cb] done

            if (tid == 0) {
                // release my slice writes cluster-wide, then signal the 7 peers
                asm volatile("fence.acq_rel.cluster;" ::: "memory");
#pragma unroll
                for (int i = 1; i < 8; i++) {
                    const int q = (r + i) & 7;
                    const unsigned mb = pbase[q] + MBAR_OFF + (unsigned)((nb * 8 + r) * 8);
                    asm volatile("mbarrier.arrive.shared::cluster.b64 _, [%0];"
                                 :: "r"(mb) : "memory");
                }
            }
        } else {
            // final step: publish my value straight to gmem for the readout
            asm volatile("st.global.cg.f32 [%0], %1;"
                         :: "l"(g_buf + (size_t)cl * 4096 + gh * 8 + bb), "f"(mn) : "memory");
        }
    }

    // spike-count reduction (512 threads)
    __syncthreads();
    part[tid] = cnt;
    __syncthreads();
    if (tid < 256) part[tid] += part[tid + 256];
    __syncthreads();
    if (tid < 128) part[tid] += part[tid + 128];
    __syncthreads();
    if (tid < 64) part[tid] += part[tid + 64];
    __syncthreads();
    if (tid < 32) {
        float v = part[tid] + part[tid + 32];
#pragma unroll
        for (int o = 16; o > 0; o >>= 1) v += __shfl_down_sync(0xffffffffu, v, o);
        if (tid == 0) atomicAdd(&g_cnt, (int)(v + 0.5f));
    }
    CLUSTER_BARRIER();   // no CTA exits while peers may still remote-read its smem
}

// ---------------- Phase 3: readout GEMM + sparsity ----------------
// final mem: mem[b][h] = g_buf[(b>>3)*4096 + h*8 + (b&7)]
__global__ void readout_kernel(const float* __restrict__ Wro, const float* __restrict__ bro,
                               float* __restrict__ out, int out_size)
{
    __shared__ float mrow[512];
    const int row = blockIdx.x;
    const int tid = threadIdx.x;   // 128
    const float* src = g_buf + (size_t)(row >> 3) * 4096 + (row & 7);
    for (int i = tid; i < 512; i += 128) mrow[i] = src[i * 8];
    __syncthreads();
    float acc = bro[tid];
#pragma unroll 8
    for (int k = 0; k < 512; k++)
        acc = fmaf(mrow[k], Wro[(size_t)k * 128 + tid], acc);
    out[(size_t)row * 128 + tid] = acc;
    if (row == 0 && tid == 0 && out_size > B_SZ * C_OUT) {
        out[B_SZ * C_OUT] = 1.0f - (float)g_cnt / (float)((size_t)S_LEN * B_SZ * H_SZ);
    }
}

// ---------------- launch ----------------
extern "C" void kernel_launch(void* const* d_in, const int* in_sizes, int n_in,
                              void* d_out, int out_size)
{
    const float* x    = (const float*)d_in[0];
    const float* Win  = (const float*)d_in[1];
    const float* bin  = (const float*)d_in[2];
    const float* Wtau = (const float*)d_in[3];
    const float* btl  = (const float*)d_in[4];
    const float* bt   = (const float*)d_in[5];
    const float* Wro  = (const float*)d_in[6];
    const float* bro  = (const float*)d_in[7];

    init_kernel<<<1, 1>>>();

    dim3 g1(8, 1024);   // n-tiles x m-tiles
    phase1_kernel<<<g1, 256>>>(x, Win, bin, Wtau, btl, bt);

    cudaFuncSetAttribute(recurrent_kernel, cudaFuncAttributeMaxDynamicSharedMemorySize, REC_SMEM);
    recurrent_kernel<<<128, 512, REC_SMEM>>>(Wtau);

    readout_kernel<<<B_SZ, C_OUT>>>(Wro, bro, (float*)d_out, out_size);
}

// round 10
// speedup vs baseline: 1.2078x; 1.2078x over previous
#include <cuda_runtime.h>
#include <cstdint>
#include <cstdio>

#define S_LEN 1024
#define B_SZ  128
#define D_IN  256
#define H_SZ  512
#define C_OUT 128

typedef unsigned long long ull;

// ---------------- f32x2 packed-FMA helpers (bit-identical per lane) ----------------
__device__ __forceinline__ ull ffma2(ull a, ull b, ull c) {
    ull d;
    asm("fma.rn.f32x2 %0, %1, %2, %3;" : "=l"(d) : "l"(a), "l"(b), "l"(c));
    return d;
}
__device__ __forceinline__ ull dup2(float v) {
    ull d;
    asm("mov.b64 %0, {%1, %1};" : "=l"(d) : "f"(v));
    return d;
}
__device__ __forceinline__ float2 unpack2(ull p) {
    float2 r;
    asm("mov.b64 {%0, %1}, %2;" : "=f"(r.x), "=f"(r.y) : "l"(p));
    return r;
}

// ---------------- device scratch ----------------
__device__ float g_T[(size_t)S_LEN * B_SZ * H_SZ];   // x@W_tau_x + b_tau_lin + b_tau
__device__ float g_G[(size_t)S_LEN * B_SZ * H_SZ];   // x@W_in + b_in
__device__ float g_buf[16 * 512 * 8];                // final mem: [cluster][h][b]
__device__ int   g_cnt;

__global__ void init_kernel() { g_cnt = 0; }

// ---------------- Phase 1: fused precompute GEMM (FFMA2 over n-pairs; bit-identical) ----------------
__global__ __launch_bounds__(256, 2) void phase1_kernel(
    const float* __restrict__ x, const float* __restrict__ Win,
    const float* __restrict__ bin, const float* __restrict__ Wtau,
    const float* __restrict__ btl, const float* __restrict__ bt)
{
    __shared__ float As[2][16][128];   // As[k][m]
    __shared__ float Bs[2][16][128];   // Bs[k][n]

    const int tid = threadIdx.x;
    const int m0 = blockIdx.y * 128;
    const int n0 = blockIdx.x * 128;
    const bool isG = (n0 < 512);
    const float* __restrict__ Bp = isG ? (Win + n0) : (Wtau + (n0 - 512));

    const int q0 = tid, q1 = tid + 256;
    const int ar0 = q0 >> 2, ak0 = (q0 & 3) * 4;
    const int ar1 = q1 >> 2, ak1 = (q1 & 3) * 4;
    const int m_0 = m0 + ar0, m_1 = m0 + ar1;
    const float* ap0 = x + ((size_t)(m_0 & 127) * 1024 + (m_0 >> 7)) * 256 + ak0;
    const float* ap1 = x + ((size_t)(m_1 & 127) * 1024 + (m_1 >> 7)) * 256 + ak1;
    const int bk0 = q0 >> 5, bn0 = (q0 & 31) * 4;
    const int bk1 = q1 >> 5, bn1 = (q1 & 31) * 4;

    const int tx = tid & 15, ty = tid >> 4;
    const int c0 = tx * 4, c1 = tx * 4 + 64;
    const int r0 = ty * 4, r1 = ty * 4 + 64;

    ull acc2[8][4];
#pragma unroll
    for (int i = 0; i < 8; i++)
#pragma unroll
        for (int j = 0; j < 4; j++) acc2[i][j] = 0ull;

    float4 pa0 = *(const float4*)(ap0);
    float4 pa1 = *(const float4*)(ap1);
    float4 pb0 = *(const float4*)(Bp + (size_t)bk0 * 512 + bn0);
    float4 pb1 = *(const float4*)(Bp + (size_t)bk1 * 512 + bn1);

    As[0][ak0 + 0][ar0] = pa0.x; As[0][ak0 + 1][ar0] = pa0.y;
    As[0][ak0 + 2][ar0] = pa0.z; As[0][ak0 + 3][ar0] = pa0.w;
    As[0][ak1 + 0][ar1] = pa1.x; As[0][ak1 + 1][ar1] = pa1.y;
    As[0][ak1 + 2][ar1] = pa1.z; As[0][ak1 + 3][ar1] = pa1.w;
    *(float4*)&Bs[0][bk0][bn0] = pb0;
    *(float4*)&Bs[0][bk1][bn1] = pb1;
    __syncthreads();

    int p = 0;
    for (int kt = 0; kt < 16; kt++) {
        if (kt < 15) {
            const int kc = (kt + 1) * 16;
            pa0 = *(const float4*)(ap0 + kc);
            pa1 = *(const float4*)(ap1 + kc);
            pb0 = *(const float4*)(Bp + (size_t)(kc + bk0) * 512 + bn0);
            pb1 = *(const float4*)(Bp + (size_t)(kc + bk1) * 512 + bn1);
        }
#pragma unroll
        for (int k = 0; k < 16; k++) {
            float4 a0 = *(const float4*)&As[p][k][r0];
            float4 a1 = *(const float4*)&As[p][k][r1];
            const ull* bu0 = (const ull*)&Bs[p][k][c0];
            const ull* bu1 = (const ull*)&Bs[p][k][c1];
            ull bv[4] = {bu0[0], bu0[1], bu1[0], bu1[1]};
            float av[8] = {a0.x, a0.y, a0.z, a0.w, a1.x, a1.y, a1.z, a1.w};
#pragma unroll
            for (int i = 0; i < 8; i++) {
                const ull ad = dup2(av[i]);
#pragma unroll
                for (int j = 0; j < 4; j++)
                    acc2[i][j] = ffma2(ad, bv[j], acc2[i][j]);
            }
        }
        if (kt < 15) {
            const int np = p ^ 1;
            As[np][ak0 + 0][ar0] = pa0.x; As[np][ak0 + 1][ar0] = pa0.y;
            As[np][ak0 + 2][ar0] = pa0.z; As[np][ak0 + 3][ar0] = pa0.w;
            As[np][ak1 + 0][ar1] = pa1.x; As[np][ak1 + 1][ar1] = pa1.y;
            As[np][ak1 + 2][ar1] = pa1.z; As[np][ak1 + 3][ar1] = pa1.w;
            *(float4*)&Bs[np][bk0][bn0] = pb0;
            *(float4*)&Bs[np][bk1][bn1] = pb1;
        }
        __syncthreads();
        p ^= 1;
    }

    float* dst = isG ? g_G : g_T;
    const int coloff = isG ? n0 : (n0 - 512);
    float bias[8];
#pragma unroll
    for (int j = 0; j < 8; j++) {
        const int ncol = (j < 4) ? (c0 + j) : (c1 + j - 4);
        const int gb = coloff + ncol;
        bias[j] = isG ? bin[gb] : (btl[gb] + bt[gb]);
    }
#pragma unroll
    for (int i = 0; i < 8; i++) {
        const int mrow = m0 + ((i < 4) ? (r0 + i) : (r1 + i - 4));
        float2 u0 = unpack2(acc2[i][0]);
        float2 u1 = unpack2(acc2[i][1]);
        float2 u2 = unpack2(acc2[i][2]);
        float2 u3 = unpack2(acc2[i][3]);
        float4 o0 = make_float4(u0.x + bias[0], u0.y + bias[1],
                                u1.x + bias[2], u1.y + bias[3]);
        float4 o1 = make_float4(u2.x + bias[4], u2.y + bias[5],
                                u3.x + bias[6], u3.y + bias[7]);
        *(float4*)(dst + (size_t)mrow * 512 + coloff + c0) = o0;
        *(float4*)(dst + (size_t)mrow * 512 + coloff + c1) = o1;
    }
}

// ---------------- Phase 2: persistent recurrent kernel (R7 verbatim) ----------------
__device__ __forceinline__ unsigned smem_u32_addr(const void* p) {
    unsigned a;
    asm("{ .reg .u64 t; cvta.to.shared.u64 t, %1; cvt.u32.u64 %0, t; }"
        : "=r"(a) : "l"(p));
    return a;
}

#define CLUSTER_BARRIER() \
    asm volatile("barrier.cluster.arrive.aligned;\n\tbarrier.cluster.wait.aligned;" ::: "memory")

// smem layout offsets (bytes)
#define WM_BYTES   (512 * 64 * 4)              // 131072
#define MEMB_OFF   WM_BYTES                    // [2][512][8] floats
#define MEMB_BYTES (2 * 512 * 8 * 4)           // 32768
#define PART_OFF   (MEMB_OFF + MEMB_BYTES)     // [16][512] floats
#define PART_BYTES (16 * 512 * 4)              // 32768
#define MBAR_OFF   (PART_OFF + PART_BYTES)     // [2][8] x u64  (buffer, source rank)
#define REC_SMEM   (MBAR_OFF + 128)

__global__ void __cluster_dims__(8, 1, 1) __launch_bounds__(512, 1)
recurrent_kernel(const float* __restrict__ Wtau)
{
    extern __shared__ float sm[];
    float* Wm   = sm;                          // [512][64]   128 KB (k-major, 64 cols)
    float* memB = sm + 512 * 64;               // [2][512][8]  32 KB (h-major, batch contiguous)
    float* part = memB + 2 * 512 * 8;          // [16][512]    32 KB

    const int tid  = threadIdx.x;
    const int lane = tid & 31;
    const int w    = tid >> 5;                 // 0..15
    const int r    = blockIdx.x & 7;           // cluster rank -> column slice
    const int cl   = blockIdx.x >> 3;          // cluster index -> 8 batch rows
    const int b0   = cl * 8;

    // Load W_tau_m slice: rows 256..767, cols r*64..r*64+63
    for (int idx = tid; idx < 512 * 64; idx += 512) {
        const int k = idx >> 6, c = idx & 63;
        Wm[idx] = Wtau[(size_t)(256 + k) * 512 + r * 64 + c];
    }
    // Zero both mem buffers (t=0 input)
    for (int idx = tid; idx < 2 * 512 * 8; idx += 512) memB[idx] = 0.f;

    const unsigned sbase = smem_u32_addr(sm);
    const unsigned mbar_base = sbase + MBAR_OFF;
    if (tid < 16) {
        asm volatile("mbarrier.init.shared.b64 [%0], %1;"
                     :: "r"(mbar_base + tid * 8), "r"(1) : "memory");
    }
    // hoisted mapa: smem base of every cluster CTA
    unsigned pbase[8];
#pragma unroll
    for (int q = 0; q < 8; q++)
        asm("mapa.shared::cluster.u32 %0, %1, %2;" : "=r"(pbase[q]) : "r"(sbase), "r"(q));

    CLUSTER_BARRIER();   // mbar init + memB zero visible cluster-wide

    // elementwise role: one cell (bb, ce) per thread
    const int ce = tid & 63;
    const int bb = tid >> 6;                   // batch 0..7
    const int gh = r * 64 + ce;                // global hidden col
    const int k0 = w * 32;                     // warp K-split (32 k's per warp)
    const int src = w >> 1;                    // the ONLY source rank this warp's k-range needs
    const unsigned my_mbar_b0 = mbar_base + (unsigned)(src * 8);
    const unsigned my_mbar_b1 = mbar_base + (unsigned)(64 + src * 8);

    float cnt = 0.f;

    for (int t = 0; t < S_LEN; t++) {
        const int cb = t & 1, nb = cb ^ 1;

        // prefetch T/G (consumed after GEMM)
        const size_t row = ((size_t)t * B_SZ + b0 + bb) * H_SZ + gh;
        const float Tv = g_T[row], Gv = g_G[row];

        // ---- per-warp wait: only my source slice of buffer cb must have landed ----
        if (t > 0) {
            const unsigned ph = (unsigned)(((t - 1) >> 1) & 1);
            const unsigned mb = cb ? my_mbar_b1 : my_mbar_b0;
            asm volatile(
                "{\n\t"
                ".reg .pred P;\n\t"
                "W_%=:\n\t"
                "mbarrier.try_wait.parity.acquire.cta.shared::cta.b64 P, [%0], %1, 0x989680;\n\t"
                "@P bra D_%=;\n\t"
                "bra W_%=;\n\t"
                "D_%=:\n\t"
                "}"
                :: "r"(mb), "r"(ph) : "memory");
        }

        // ---- GEMM: out[b][c] = sum_k memB[cb][k][b] * Wm[k][c] (warp K-split) ----
        float acc_a[8], acc_b[8];
#pragma unroll
        for (int b = 0; b < 8; b++) { acc_a[b] = 0.f; acc_b[b] = 0.f; }

        const float* mp = memB + cb * 4096 + k0 * 8;
        const float* wp = Wm + k0 * 64;
#pragma unroll 4
        for (int kk = 0; kk < 32; kk += 4) {
            float rm[4][8];
#pragma unroll
            for (int j = 0; j < 4; j++) {
                float4 v0 = *(const float4*)(mp + (kk + j) * 8);
                float4 v1 = *(const float4*)(mp + (kk + j) * 8 + 4);
                rm[j][0] = v0.x; rm[j][1] = v0.y; rm[j][2] = v0.z; rm[j][3] = v0.w;
                rm[j][4] = v1.x; rm[j][5] = v1.y; rm[j][6] = v1.z; rm[j][7] = v1.w;
            }
#pragma unroll
            for (int j = 0; j < 4; j++) {
                const float2 wv = *(const float2*)(wp + (kk + j) * 64 + 2 * lane);
#pragma unroll
                for (int b = 0; b < 8; b++) {
                    acc_a[b] = fmaf(rm[j][b], wv.x, acc_a[b]);
                    acc_b[b] = fmaf(rm[j][b], wv.y, acc_b[b]);
                }
            }
        }
        // warp partials: part[w][b*64 + 2*lane .. +1]
#pragma unroll
        for (int b = 0; b < 8; b++) {
            *(float2*)&part[w * 512 + b * 64 + 2 * lane] = make_float2(acc_a[b], acc_b[b]);
        }
        __syncthreads();

        // ---- reduce 16 warp partials + elementwise update for cell (bb, ce) ----
        float s = 0.f;
#pragma unroll
        for (int ww = 0; ww < 16; ww++)
            s += part[ww * 512 + bb * 64 + ce];
        const float l = Tv + s;
        float beta = 1.f / (1.f + expf(-l));
        beta = fminf(fmaxf(beta, 0.01f), 0.99f);
        const float mo = memB[cb * 4096 + gh * 8 + bb];
        float mn = fmaf(beta, mo, Gv);
        const float sp = ((mn - 1.0f) > 0.0f) ? 1.f : 0.f;
        mn -= sp;
        cnt += sp;

        if (t < S_LEN - 1) {
            // write my slice into my own next buffer
            memB[nb * 4096 + gh * 8 + bb] = mn;
            __syncthreads();   // slice fully written; all GEMM reads of memB[cb] done too

            if (tid == 0) {
                asm volatile("fence.proxy.async;" ::: "memory");
                // arm my 8 per-source barriers for buffer nb
#pragma unroll
                for (int q = 0; q < 8; q++) {
                    const unsigned mb = mbar_base + (unsigned)((nb * 8 + q) * 8);
                    if (q == r) {
                        asm volatile("mbarrier.arrive.shared.b64 _, [%0];"
                                     :: "r"(mb) : "memory");
                    } else {
                        asm volatile("mbarrier.arrive.expect_tx.shared.b64 _, [%0], %1;"
                                     :: "r"(mb), "r"(2048) : "memory");
                    }
                }
                // send my 2KB slice to the 7 peers; complete THEIR mbar[nb][r]
                const unsigned srcaddr = sbase + MEMB_OFF + (unsigned)(nb * 16384 + r * 2048);
                const unsigned doff = MEMB_OFF + (unsigned)(nb * 16384 + r * 2048);
                const unsigned moff = MBAR_OFF + (unsigned)((nb * 8 + r) * 8);
#pragma unroll
                for (int i = 1; i < 8; i++) {
                    const int q = (r + i) & 7;
                    asm volatile(
                        "cp.async.bulk.shared::cluster.shared::cta.mbarrier::complete_tx::bytes"
                        " [%0], [%1], %2, [%3];"
                        :: "r"(pbase[q] + doff), "r"(srcaddr), "r"(2048), "r"(pbase[q] + moff)
                        : "memory");
                }
            }
            // NO cluster-wide wait here: each warp waits on its own slice next step.
        } else {
            // final step: publish my value straight to gmem for the readout
            asm volatile("st.global.cg.f32 [%0], %1;"
                         :: "l"(g_buf + (size_t)cl * 4096 + gh * 8 + bb), "f"(mn) : "memory");
        }
    }

    // spike-count reduction (512 threads)
    __syncthreads();
    part[tid] = cnt;
    __syncthreads();
    if (tid < 256) part[tid] += part[tid + 256];
    __syncthreads();
    if (tid < 128) part[tid] += part[tid + 128];
    __syncthreads();
    if (tid < 64) part[tid] += part[tid + 64];
    __syncthreads();
    if (tid < 32) {
        float v = part[tid] + part[tid + 32];
#pragma unroll
        for (int o = 16; o > 0; o >>= 1) v += __shfl_down_sync(0xffffffffu, v, o);
        if (tid == 0) atomicAdd(&g_cnt, (int)(v + 0.5f));
    }
    CLUSTER_BARRIER();   // no CTA exits while peers' copies may still target its smem
}

// ---------------- Phase 3: readout GEMM + sparsity ----------------
// final mem: mem[b][h] = g_buf[(b>>3)*4096 + h*8 + (b&7)]
__global__ void readout_kernel(const float* __restrict__ Wro, const float* __restrict__ bro,
                               float* __restrict__ out, int out_size)
{
    __shared__ float mrow[512];
    const int row = blockIdx.x;
    const int tid = threadIdx.x;   // 128
    const float* src = g_buf + (size_t)(row >> 3) * 4096 + (row & 7);
    for (int i = tid; i < 512; i += 128) mrow[i] = src[i * 8];
    __syncthreads();
    float acc = bro[tid];
#pragma unroll 8
    for (int k = 0; k < 512; k++)
        acc = fmaf(mrow[k], Wro[(size_t)k * 128 + tid], acc);
    out[(size_t)row * 128 + tid] = acc;
    if (row == 0 && tid == 0 && out_size > B_SZ * C_OUT) {
        out[B_SZ * C_OUT] = 1.0f - (float)g_cnt / (float)((size_t)S_LEN * B_SZ * H_SZ);
    }
}

// ---------------- launch ----------------
extern "C" void kernel_launch(void* const* d_in, const int* in_sizes, int n_in,
                              void* d_out, int out_size)
{
    const float* x    = (const float*)d_in[0];
    const float* Win  = (const float*)d_in[1];
    const float* bin  = (const float*)d_in[2];
    const float* Wtau = (const float*)d_in[3];
    const float* btl  = (const float*)d_in[4];
    const float* bt   = (const float*)d_in[5];
    const float* Wro  = (const float*)d_in[6];
    const float* bro  = (const float*)d_in[7];

    init_kernel<<<1, 1>>>();

    dim3 g1(8, 1024);   // n-tiles x m-tiles
    phase1_kernel<<<g1, 256>>>(x, Win, bin, Wtau, btl, bt);

    cudaFuncSetAttribute(recurrent_kernel, cudaFuncAttributeMaxDynamicSharedMemorySize, REC_SMEM);
    recurrent_kernel<<<128, 512, REC_SMEM>>>(Wtau);

    readout_kernel<<<B_SZ, C_OUT>>>(Wro, bro, (float*)d_out, out_size);
}

// round 11
// speedup vs baseline: 1.2333x; 1.0212x over previous
#include <cuda_runtime.h>
#include <cstdint>
#include <cstdio>

#define S_LEN 1024
#define B_SZ  128
#define D_IN  256
#define H_SZ  512
#define C_OUT 128

typedef unsigned long long ull;

// ---------------- f32x2 packed-FMA helpers (bit-identical per lane) ----------------
__device__ __forceinline__ ull ffma2(ull a, ull b, ull c) {
    ull d;
    asm("fma.rn.f32x2 %0, %1, %2, %3;" : "=l"(d) : "l"(a), "l"(b), "l"(c));
    return d;
}
__device__ __forceinline__ ull dup2(float v) {
    ull d;
    asm("mov.b64 %0, {%1, %1};" : "=l"(d) : "f"(v));
    return d;
}
__device__ __forceinline__ float2 unpack2(ull p) {
    float2 r;
    asm("mov.b64 {%0, %1}, %2;" : "=f"(r.x), "=f"(r.y) : "l"(p));
    return r;
}

// ---------------- device scratch ----------------
__device__ float g_T[(size_t)S_LEN * B_SZ * H_SZ];   // x@W_tau_x + b_tau_lin + b_tau
__device__ float g_G[(size_t)S_LEN * B_SZ * H_SZ];   // x@W_in + b_in
__device__ float g_buf[16 * 512 * 8];                // final mem: [cluster][h][b]
__device__ int   g_cnt;

__global__ void init_kernel() { g_cnt = 0; }

// ---------------- Phase 1: fused precompute GEMM (FFMA2 over n-pairs; bit-identical) ----------------
__global__ __launch_bounds__(256, 2) void phase1_kernel(
    const float* __restrict__ x, const float* __restrict__ Win,
    const float* __restrict__ bin, const float* __restrict__ Wtau,
    const float* __restrict__ btl, const float* __restrict__ bt)
{
    __shared__ float As[2][16][128];   // As[k][m]
    __shared__ float Bs[2][16][128];   // Bs[k][n]

    const int tid = threadIdx.x;
    const int m0 = blockIdx.y * 128;
    const int n0 = blockIdx.x * 128;
    const bool isG = (n0 < 512);
    const float* __restrict__ Bp = isG ? (Win + n0) : (Wtau + (n0 - 512));

    const int q0 = tid, q1 = tid + 256;
    const int ar0 = q0 >> 2, ak0 = (q0 & 3) * 4;
    const int ar1 = q1 >> 2, ak1 = (q1 & 3) * 4;
    const int m_0 = m0 + ar0, m_1 = m0 + ar1;
    const float* ap0 = x + ((size_t)(m_0 & 127) * 1024 + (m_0 >> 7)) * 256 + ak0;
    const float* ap1 = x + ((size_t)(m_1 & 127) * 1024 + (m_1 >> 7)) * 256 + ak1;
    const int bk0 = q0 >> 5, bn0 = (q0 & 31) * 4;
    const int bk1 = q1 >> 5, bn1 = (q1 & 31) * 4;

    const int tx = tid & 15, ty = tid >> 4;
    const int c0 = tx * 4, c1 = tx * 4 + 64;
    const int r0 = ty * 4, r1 = ty * 4 + 64;

    ull acc2[8][4];
#pragma unroll
    for (int i = 0; i < 8; i++)
#pragma unroll
        for (int j = 0; j < 4; j++) acc2[i][j] = 0ull;

    float4 pa0 = *(const float4*)(ap0);
    float4 pa1 = *(const float4*)(ap1);
    float4 pb0 = *(const float4*)(Bp + (size_t)bk0 * 512 + bn0);
    float4 pb1 = *(const float4*)(Bp + (size_t)bk1 * 512 + bn1);

    As[0][ak0 + 0][ar0] = pa0.x; As[0][ak0 + 1][ar0] = pa0.y;
    As[0][ak0 + 2][ar0] = pa0.z; As[0][ak0 + 3][ar0] = pa0.w;
    As[0][ak1 + 0][ar1] = pa1.x; As[0][ak1 + 1][ar1] = pa1.y;
    As[0][ak1 + 2][ar1] = pa1.z; As[0][ak1 + 3][ar1] = pa1.w;
    *(float4*)&Bs[0][bk0][bn0] = pb0;
    *(float4*)&Bs[0][bk1][bn1] = pb1;
    __syncthreads();

    int p = 0;
    for (int kt = 0; kt < 16; kt++) {
        if (kt < 15) {
            const int kc = (kt + 1) * 16;
            pa0 = *(const float4*)(ap0 + kc);
            pa1 = *(const float4*)(ap1 + kc);
            pb0 = *(const float4*)(Bp + (size_t)(kc + bk0) * 512 + bn0);
            pb1 = *(const float4*)(Bp + (size_t)(kc + bk1) * 512 + bn1);
        }
#pragma unroll
        for (int k = 0; k < 16; k++) {
            float4 a0 = *(const float4*)&As[p][k][r0];
            float4 a1 = *(const float4*)&As[p][k][r1];
            const ull* bu0 = (const ull*)&Bs[p][k][c0];
            const ull* bu1 = (const ull*)&Bs[p][k][c1];
            ull bv[4] = {bu0[0], bu0[1], bu1[0], bu1[1]};
            float av[8] = {a0.x, a0.y, a0.z, a0.w, a1.x, a1.y, a1.z, a1.w};
#pragma unroll
            for (int i = 0; i < 8; i++) {
                const ull ad = dup2(av[i]);
#pragma unroll
                for (int j = 0; j < 4; j++)
                    acc2[i][j] = ffma2(ad, bv[j], acc2[i][j]);
            }
        }
        if (kt < 15) {
            const int np = p ^ 1;
            As[np][ak0 + 0][ar0] = pa0.x; As[np][ak0 + 1][ar0] = pa0.y;
            As[np][ak0 + 2][ar0] = pa0.z; As[np][ak0 + 3][ar0] = pa0.w;
            As[np][ak1 + 0][ar1] = pa1.x; As[np][ak1 + 1][ar1] = pa1.y;
            As[np][ak1 + 2][ar1] = pa1.z; As[np][ak1 + 3][ar1] = pa1.w;
            *(float4*)&Bs[np][bk0][bn0] = pb0;
            *(float4*)&Bs[np][bk1][bn1] = pb1;
        }
        __syncthreads();
        p ^= 1;
    }

    float* dst = isG ? g_G : g_T;
    const int coloff = isG ? n0 : (n0 - 512);
    float bias[8];
#pragma unroll
    for (int j = 0; j < 8; j++) {
        const int ncol = (j < 4) ? (c0 + j) : (c1 + j - 4);
        const int gb = coloff + ncol;
        bias[j] = isG ? bin[gb] : (btl[gb] + bt[gb]);
    }
#pragma unroll
    for (int i = 0; i < 8; i++) {
        const int mrow = m0 + ((i < 4) ? (r0 + i) : (r1 + i - 4));
        float2 u0 = unpack2(acc2[i][0]);
        float2 u1 = unpack2(acc2[i][1]);
        float2 u2 = unpack2(acc2[i][2]);
        float2 u3 = unpack2(acc2[i][3]);
        float4 o0 = make_float4(u0.x + bias[0], u0.y + bias[1],
                                u1.x + bias[2], u1.y + bias[3]);
        float4 o1 = make_float4(u2.x + bias[4], u2.y + bias[5],
                                u3.x + bias[6], u3.y + bias[7]);
        *(float4*)(dst + (size_t)mrow * 512 + coloff + c0) = o0;
        *(float4*)(dst + (size_t)mrow * 512 + coloff + c1) = o1;
    }
}

// ---------------- Phase 2: persistent recurrent kernel (R7 structure, FFMA2 inner loop) ----------------
__device__ __forceinline__ unsigned smem_u32_addr(const void* p) {
    unsigned a;
    asm("{ .reg .u64 t; cvta.to.shared.u64 t, %1; cvt.u32.u64 %0, t; }"
        : "=r"(a) : "l"(p));
    return a;
}

#define CLUSTER_BARRIER() \
    asm volatile("barrier.cluster.arrive.aligned;\n\tbarrier.cluster.wait.aligned;" ::: "memory")

// smem layout offsets (bytes)
#define WM_BYTES   (512 * 64 * 4)              // 131072
#define MEMB_OFF   WM_BYTES                    // [2][512][8] floats
#define MEMB_BYTES (2 * 512 * 8 * 4)           // 32768
#define PART_OFF   (MEMB_OFF + MEMB_BYTES)     // [16][512] floats
#define PART_BYTES (16 * 512 * 4)              // 32768
#define MBAR_OFF   (PART_OFF + PART_BYTES)     // [2][8] x u64  (buffer, source rank)
#define REC_SMEM   (MBAR_OFF + 128)

__global__ void __cluster_dims__(8, 1, 1) __launch_bounds__(512, 1)
recurrent_kernel(const float* __restrict__ Wtau)
{
    extern __shared__ float sm[];
    float* Wm   = sm;                          // [512][64]   128 KB (k-major, 64 cols)
    float* memB = sm + 512 * 64;               // [2][512][8]  32 KB (h-major, batch contiguous)
    float* part = memB + 2 * 512 * 8;          // [16][512]    32 KB

    const int tid  = threadIdx.x;
    const int lane = tid & 31;
    const int w    = tid >> 5;                 // 0..15
    const int r    = blockIdx.x & 7;           // cluster rank -> column slice
    const int cl   = blockIdx.x >> 3;          // cluster index -> 8 batch rows
    const int b0   = cl * 8;

    // Load W_tau_m slice: rows 256..767, cols r*64..r*64+63
    for (int idx = tid; idx < 512 * 64; idx += 512) {
        const int k = idx >> 6, c = idx & 63;
        Wm[idx] = Wtau[(size_t)(256 + k) * 512 + r * 64 + c];
    }
    // Zero both mem buffers (t=0 input)
    for (int idx = tid; idx < 2 * 512 * 8; idx += 512) memB[idx] = 0.f;

    const unsigned sbase = smem_u32_addr(sm);
    const unsigned mbar_base = sbase + MBAR_OFF;
    if (tid < 16) {
        asm volatile("mbarrier.init.shared.b64 [%0], %1;"
                     :: "r"(mbar_base + tid * 8), "r"(1) : "memory");
    }
    // hoisted mapa: smem base of every cluster CTA
    unsigned pbase[8];
#pragma unroll
    for (int q = 0; q < 8; q++)
        asm("mapa.shared::cluster.u32 %0, %1, %2;" : "=r"(pbase[q]) : "r"(sbase), "r"(q));

    CLUSTER_BARRIER();   // mbar init + memB zero visible cluster-wide

    // elementwise role: one cell (bb, ce) per thread
    const int ce = tid & 63;
    const int bb = tid >> 6;                   // batch 0..7
    const int gh = r * 64 + ce;                // global hidden col
    const int k0 = w * 32;                     // warp K-split (32 k's per warp)
    const int src = w >> 1;                    // the ONLY source rank this warp's k-range needs
    const unsigned my_mbar_b0 = mbar_base + (unsigned)(src * 8);
    const unsigned my_mbar_b1 = mbar_base + (unsigned)(64 + src * 8);

    float cnt = 0.f;

    for (int t = 0; t < S_LEN; t++) {
        const int cb = t & 1, nb = cb ^ 1;

        // prefetch T/G (consumed after GEMM)
        const size_t row = ((size_t)t * B_SZ + b0 + bb) * H_SZ + gh;
        const float Tv = g_T[row], Gv = g_G[row];

        // ---- per-warp wait: only my source slice of buffer cb must have landed ----
        if (t > 0) {
            const unsigned ph = (unsigned)(((t - 1) >> 1) & 1);
            const unsigned mb = cb ? my_mbar_b1 : my_mbar_b0;
            asm volatile(
                "{\n\t"
                ".reg .pred P;\n\t"
                "W_%=:\n\t"
                "mbarrier.try_wait.parity.acquire.cta.shared::cta.b64 P, [%0], %1, 0x989680;\n\t"
                "@P bra D_%=;\n\t"
                "bra W_%=;\n\t"
                "D_%=:\n\t"
                "}"
                :: "r"(mb), "r"(ph) : "memory");
        }

        // ---- GEMM: out[b][c] = sum_k memB[cb][k][b] * Wm[k][c]  (FFMA2 over batch pairs) ----
        // pa[j] lanes = (acc_a[2j], acc_a[2j+1]); pb[j] = (acc_b[2j], acc_b[2j+1]).
        // Each output lives in its own 32-bit lane with identical ascending-k fma chain
        // -> bit-identical to the scalar version.
        ull pa[4], pb[4];
#pragma unroll
        for (int j = 0; j < 4; j++) { pa[j] = 0ull; pb[j] = 0ull; }

        const float* mp = memB + cb * 4096 + k0 * 8;
        const float* wp = Wm + k0 * 64;
#pragma unroll 4
        for (int kk = 0; kk < 32; kk++) {
            const ulonglong2 m01 = *(const ulonglong2*)(mp + kk * 8);      // (b0,b1),(b2,b3)
            const ulonglong2 m23 = *(const ulonglong2*)(mp + kk * 8 + 4);  // (b4,b5),(b6,b7)
            const float2 wv = *(const float2*)(wp + kk * 64 + 2 * lane);
            const ull w0d = dup2(wv.x);
            const ull w1d = dup2(wv.y);
            pa[0] = ffma2(m01.x, w0d, pa[0]);
            pa[1] = ffma2(m01.y, w0d, pa[1]);
            pa[2] = ffma2(m23.x, w0d, pa[2]);
            pa[3] = ffma2(m23.y, w0d, pa[3]);
            pb[0] = ffma2(m01.x, w1d, pb[0]);
            pb[1] = ffma2(m01.y, w1d, pb[1]);
            pb[2] = ffma2(m23.x, w1d, pb[2]);
            pb[3] = ffma2(m23.y, w1d, pb[3]);
        }
        // warp partials: part[w][b*64 + 2*lane .. +1]  (same layout/values as scalar version)
#pragma unroll
        for (int j = 0; j < 4; j++) {
            const float2 fa = unpack2(pa[j]);   // (acc_a[2j], acc_a[2j+1])
            const float2 fb = unpack2(pb[j]);   // (acc_b[2j], acc_b[2j+1])
            *(float2*)&part[w * 512 + (2 * j)     * 64 + 2 * lane] = make_float2(fa.x, fb.x);
            *(float2*)&part[w * 512 + (2 * j + 1) * 64 + 2 * lane] = make_float2(fa.y, fb.y);
        }
        __syncthreads();

        // ---- reduce 16 warp partials + elementwise update for cell (bb, ce) ----
        float s = 0.f;
#pragma unroll
        for (int ww = 0; ww < 16; ww++)
            s += part[ww * 512 + bb * 64 + ce];
        const float l = Tv + s;
        float beta = 1.f / (1.f + expf(-l));
        beta = fminf(fmaxf(beta, 0.01f), 0.99f);
        const float mo = memB[cb * 4096 + gh * 8 + bb];
        float mn = fmaf(beta, mo, Gv);
        const float sp = ((mn - 1.0f) > 0.0f) ? 1.f : 0.f;
        mn -= sp;
        cnt += sp;

        if (t < S_LEN - 1) {
            // write my slice into my own next buffer
            memB[nb * 4096 + gh * 8 + bb] = mn;
            __syncthreads();   // slice fully written; all GEMM reads of memB[cb] done too

            if (tid == 0) {
                asm volatile("fence.proxy.async;" ::: "memory");
                // arm my 8 per-source barriers for buffer nb
#pragma unroll
                for (int q = 0; q < 8; q++) {
                    const unsigned mb = mbar_base + (unsigned)((nb * 8 + q) * 8);
                    if (q == r) {
                        asm volatile("mbarrier.arrive.shared.b64 _, [%0];"
                                     :: "r"(mb) : "memory");
                    } else {
                        asm volatile("mbarrier.arrive.expect_tx.shared.b64 _, [%0], %1;"
                                     :: "r"(mb), "r"(2048) : "memory");
                    }
                }
                // send my 2KB slice to the 7 peers; complete THEIR mbar[nb][r]
                const unsigned srcaddr = sbase + MEMB_OFF + (unsigned)(nb * 16384 + r * 2048);
                const unsigned doff = MEMB_OFF + (unsigned)(nb * 16384 + r * 2048);
                const unsigned moff = MBAR_OFF + (unsigned)((nb * 8 + r) * 8);
#pragma unroll
                for (int i = 1; i < 8; i++) {
                    const int q = (r + i) & 7;
                    asm volatile(
                        "cp.async.bulk.shared::cluster.shared::cta.mbarrier::complete_tx::bytes"
                        " [%0], [%1], %2, [%3];"
                        :: "r"(pbase[q] + doff), "r"(srcaddr), "r"(2048), "r"(pbase[q] + moff)
                        : "memory");
                }
            }
            // NO cluster-wide wait here: each warp waits on its own slice next step.
        } else {
            // final step: publish my value straight to gmem for the readout
            asm volatile("st.global.cg.f32 [%0], %1;"
                         :: "l"(g_buf + (size_t)cl * 4096 + gh * 8 + bb), "f"(mn) : "memory");
        }
    }

    // spike-count reduction (512 threads)
    __syncthreads();
    part[tid] = cnt;
    __syncthreads();
    if (tid < 256) part[tid] += part[tid + 256];
    __syncthreads();
    if (tid < 128) part[tid] += part[tid + 128];
    __syncthreads();
    if (tid < 64) part[tid] += part[tid + 64];
    __syncthreads();
    if (tid < 32) {
        float v = part[tid] + part[tid + 32];
#pragma unroll
        for (int o = 16; o > 0; o >>= 1) v += __shfl_down_sync(0xffffffffu, v, o);
        if (tid == 0) atomicAdd(&g_cnt, (int)(v + 0.5f));
    }
    CLUSTER_BARRIER();   // no CTA exits while peers' copies may still target its smem
}

// ---------------- Phase 3: readout GEMM + sparsity ----------------
// final mem: mem[b][h] = g_buf[(b>>3)*4096 + h*8 + (b&7)]
__global__ void readout_kernel(const float* __restrict__ Wro, const float* __restrict__ bro,
                               float* __restrict__ out, int out_size)
{
    __shared__ float mrow[512];
    const int row = blockIdx.x;
    const int tid = threadIdx.x;   // 128
    const float* src = g_buf + (size_t)(row >> 3) * 4096 + (row & 7);
    for (int i = tid; i < 512; i += 128) mrow[i] = src[i * 8];
    __syncthreads();
    float acc = bro[tid];
#pragma unroll 8
    for (int k = 0; k < 512; k++)
        acc = fmaf(mrow[k], Wro[(size_t)k * 128 + tid], acc);
    out[(size_t)row * 128 + tid] = acc;
    if (row == 0 && tid == 0 && out_size > B_SZ * C_OUT) {
        out[B_SZ * C_OUT] = 1.0f - (float)g_cnt / (float)((size_t)S_LEN * B_SZ * H_SZ);
    }
}

// ---------------- launch ----------------
extern "C" void kernel_launch(void* const* d_in, const int* in_sizes, int n_in,
                              void* d_out, int out_size)
{
    const float* x    = (const float*)d_in[0];
    const float* Win  = (const float*)d_in[1];
    const float* bin  = (const float*)d_in[2];
    const float* Wtau = (const float*)d_in[3];
    const float* btl  = (const float*)d_in[4];
    const float* bt   = (const float*)d_in[5];
    const float* Wro  = (const float*)d_in[6];
    const float* bro  = (const float*)d_in[7];

    init_kernel<<<1, 1>>>();

    dim3 g1(8, 1024);   // n-tiles x m-tiles
    phase1_kernel<<<g1, 256>>>(x, Win, bin, Wtau, btl, bt);

    cudaFuncSetAttribute(recurrent_kernel, cudaFuncAttributeMaxDynamicSharedMemorySize, REC_SMEM);
    recurrent_kernel<<<128, 512, REC_SMEM>>>(Wtau);

    readout_kernel<<<B_SZ, C_OUT>>>(Wro, bro, (float*)d_out, out_size);
}

// round 12
// speedup vs baseline: 1.4014x; 1.1363x over previous
#include <cuda_runtime.h>
#include <cstdint>
#include <cstdio>

#define S_LEN 1024
#define B_SZ  128
#define D_IN  256
#define H_SZ  512
#define C_OUT 128

typedef unsigned long long ull;

// ---------------- f32x2 packed-FMA helpers (bit-identical per lane) ----------------
__device__ __forceinline__ ull ffma2(ull a, ull b, ull c) {
    ull d;
    asm("fma.rn.f32x2 %0, %1, %2, %3;" : "=l"(d) : "l"(a), "l"(b), "l"(c));
    return d;
}
__device__ __forceinline__ ull dup2(float v) {
    ull d;
    asm("mov.b64 %0, {%1, %1};" : "=l"(d) : "f"(v));
    return d;
}
__device__ __forceinline__ float2 unpack2(ull p) {
    float2 r;
    asm("mov.b64 {%0, %1}, %2;" : "=f"(r.x), "=f"(r.y) : "l"(p));
    return r;
}

// ---------------- device scratch ----------------
__device__ float g_T[(size_t)S_LEN * B_SZ * H_SZ];   // x@W_tau_x + b_tau_lin + b_tau
__device__ float g_G[(size_t)S_LEN * B_SZ * H_SZ];   // x@W_in + b_in
__device__ float g_buf[16 * 512 * 8];                // final mem: [cluster][h][b]
__device__ int   g_cnt;

__global__ void init_kernel() { g_cnt = 0; }

// ---------------- Phase 1: fused precompute GEMM (FFMA2 over n-pairs; bit-identical) ----------------
__global__ __launch_bounds__(256, 2) void phase1_kernel(
    const float* __restrict__ x, const float* __restrict__ Win,
    const float* __restrict__ bin, const float* __restrict__ Wtau,
    const float* __restrict__ btl, const float* __restrict__ bt)
{
    __shared__ float As[2][16][128];   // As[k][m]
    __shared__ float Bs[2][16][128];   // Bs[k][n]

    const int tid = threadIdx.x;
    const int m0 = blockIdx.y * 128;
    const int n0 = blockIdx.x * 128;
    const bool isG = (n0 < 512);
    const float* __restrict__ Bp = isG ? (Win + n0) : (Wtau + (n0 - 512));

    const int q0 = tid, q1 = tid + 256;
    const int ar0 = q0 >> 2, ak0 = (q0 & 3) * 4;
    const int ar1 = q1 >> 2, ak1 = (q1 & 3) * 4;
    const int m_0 = m0 + ar0, m_1 = m0 + ar1;
    const float* ap0 = x + ((size_t)(m_0 & 127) * 1024 + (m_0 >> 7)) * 256 + ak0;
    const float* ap1 = x + ((size_t)(m_1 & 127) * 1024 + (m_1 >> 7)) * 256 + ak1;
    const int bk0 = q0 >> 5, bn0 = (q0 & 31) * 4;
    const int bk1 = q1 >> 5, bn1 = (q1 & 31) * 4;

    const int tx = tid & 15, ty = tid >> 4;
    const int c0 = tx * 4, c1 = tx * 4 + 64;
    const int r0 = ty * 4, r1 = ty * 4 + 64;

    ull acc2[8][4];
#pragma unroll
    for (int i = 0; i < 8; i++)
#pragma unroll
        for (int j = 0; j < 4; j++) acc2[i][j] = 0ull;

    float4 pa0 = *(const float4*)(ap0);
    float4 pa1 = *(const float4*)(ap1);
    float4 pb0 = *(const float4*)(Bp + (size_t)bk0 * 512 + bn0);
    float4 pb1 = *(const float4*)(Bp + (size_t)bk1 * 512 + bn1);

    As[0][ak0 + 0][ar0] = pa0.x; As[0][ak0 + 1][ar0] = pa0.y;
    As[0][ak0 + 2][ar0] = pa0.z; As[0][ak0 + 3][ar0] = pa0.w;
    As[0][ak1 + 0][ar1] = pa1.x; As[0][ak1 + 1][ar1] = pa1.y;
    As[0][ak1 + 2][ar1] = pa1.z; As[0][ak1 + 3][ar1] = pa1.w;
    *(float4*)&Bs[0][bk0][bn0] = pb0;
    *(float4*)&Bs[0][bk1][bn1] = pb1;
    __syncthreads();

    int p = 0;
    for (int kt = 0; kt < 16; kt++) {
        if (kt < 15) {
            const int kc = (kt + 1) * 16;
            pa0 = *(const float4*)(ap0 + kc);
            pa1 = *(const float4*)(ap1 + kc);
            pb0 = *(const float4*)(Bp + (size_t)(kc + bk0) * 512 + bn0);
            pb1 = *(const float4*)(Bp + (size_t)(kc + bk1) * 512 + bn1);
        }
#pragma unroll
        for (int k = 0; k < 16; k++) {
            float4 a0 = *(const float4*)&As[p][k][r0];
            float4 a1 = *(const float4*)&As[p][k][r1];
            const ull* bu0 = (const ull*)&Bs[p][k][c0];
            const ull* bu1 = (const ull*)&Bs[p][k][c1];
            ull bv[4] = {bu0[0], bu0[1], bu1[0], bu1[1]};
            float av[8] = {a0.x, a0.y, a0.z, a0.w, a1.x, a1.y, a1.z, a1.w};
#pragma unroll
            for (int i = 0; i < 8; i++) {
                const ull ad = dup2(av[i]);
#pragma unroll
                for (int j = 0; j < 4; j++)
                    acc2[i][j] = ffma2(ad, bv[j], acc2[i][j]);
            }
        }
        if (kt < 15) {
            const int np = p ^ 1;
            As[np][ak0 + 0][ar0] = pa0.x; As[np][ak0 + 1][ar0] = pa0.y;
            As[np][ak0 + 2][ar0] = pa0.z; As[np][ak0 + 3][ar0] = pa0.w;
            As[np][ak1 + 0][ar1] = pa1.x; As[np][ak1 + 1][ar1] = pa1.y;
            As[np][ak1 + 2][ar1] = pa1.z; As[np][ak1 + 3][ar1] = pa1.w;
            *(float4*)&Bs[np][bk0][bn0] = pb0;
            *(float4*)&Bs[np][bk1][bn1] = pb1;
        }
        __syncthreads();
        p ^= 1;
    }

    float* dst = isG ? g_G : g_T;
    const int coloff = isG ? n0 : (n0 - 512);
    float bias[8];
#pragma unroll
    for (int j = 0; j < 8; j++) {
        const int ncol = (j < 4) ? (c0 + j) : (c1 + j - 4);
        const int gb = coloff + ncol;
        bias[j] = isG ? bin[gb] : (btl[gb] + bt[gb]);
    }
#pragma unroll
    for (int i = 0; i < 8; i++) {
        const int mrow = m0 + ((i < 4) ? (r0 + i) : (r1 + i - 4));
        float2 u0 = unpack2(acc2[i][0]);
        float2 u1 = unpack2(acc2[i][1]);
        float2 u2 = unpack2(acc2[i][2]);
        float2 u3 = unpack2(acc2[i][3]);
        float4 o0 = make_float4(u0.x + bias[0], u0.y + bias[1],
                                u1.x + bias[2], u1.y + bias[3]);
        float4 o1 = make_float4(u2.x + bias[4], u2.y + bias[5],
                                u3.x + bias[6], u3.y + bias[7]);
        *(float4*)(dst + (size_t)mrow * 512 + coloff + c0) = o0;
        *(float4*)(dst + (size_t)mrow * 512 + coloff + c1) = o1;
    }
}

// ---------------- Phase 2: persistent recurrent kernel (weights in registers) ----------------
__device__ __forceinline__ unsigned smem_u32_addr(const void* p) {
    unsigned a;
    asm("{ .reg .u64 t; cvta.to.shared.u64 t, %1; cvt.u32.u64 %0, t; }"
        : "=r"(a) : "l"(p));
    return a;
}

#define CLUSTER_BARRIER() \
    asm volatile("barrier.cluster.arrive.aligned;\n\tbarrier.cluster.wait.aligned;" ::: "memory")

// smem layout offsets (bytes) — Wm removed (weights live in registers)
#define MEMB_OFF   0                           // [2][512][8] floats
#define MEMB_BYTES (2 * 512 * 8 * 4)           // 32768
#define PART_OFF   (MEMB_OFF + MEMB_BYTES)     // [16][512] floats
#define PART_BYTES (16 * 512 * 4)              // 32768
#define MBAR_OFF   (PART_OFF + PART_BYTES)     // [2][8] x u64  (buffer, source rank)
#define REC_SMEM   (MBAR_OFF + 128)

__global__ void __cluster_dims__(8, 1, 1) __launch_bounds__(512, 1)
recurrent_kernel(const float* __restrict__ Wtau)
{
    extern __shared__ float sm[];
    float* memB = sm;                          // [2][512][8]  32 KB (h-major, batch contiguous)
    float* part = memB + 2 * 512 * 8;          // [16][512]    32 KB

    const int tid  = threadIdx.x;
    const int lane = tid & 31;
    const int w    = tid >> 5;                 // 0..15
    const int r    = blockIdx.x & 7;           // cluster rank -> column slice
    const int cl   = blockIdx.x >> 3;          // cluster index -> 8 batch rows
    const int b0   = cl * 8;

    const int k0 = w * 32;                     // warp K-split (32 k's per warp)

    // Weights in registers: this thread needs Wm[k0+kk][2*lane], Wm[k0+kk][2*lane+1]
    // = Wtau[(256 + k0 + kk)*512 + r*64 + 2*lane + {0,1}], kk = 0..31
    float wreg[64];
    {
        const float* wsrc = Wtau + (size_t)(256 + k0) * 512 + r * 64 + 2 * lane;
#pragma unroll
        for (int kk = 0; kk < 32; kk++) {
            const float2 wv = *(const float2*)(wsrc + (size_t)kk * 512);
            wreg[2 * kk]     = wv.x;
            wreg[2 * kk + 1] = wv.y;
        }
    }

    // Zero both mem buffers (t=0 input)
    for (int idx = tid; idx < 2 * 512 * 8; idx += 512) memB[idx] = 0.f;

    const unsigned sbase = smem_u32_addr(sm);
    const unsigned mbar_base = sbase + MBAR_OFF;
    if (tid < 16) {
        asm volatile("mbarrier.init.shared.b64 [%0], %1;"
                     :: "r"(mbar_base + tid * 8), "r"(1) : "memory");
    }
    // hoisted mapa: smem base of every cluster CTA
    unsigned pbase[8];
#pragma unroll
    for (int q = 0; q < 8; q++)
        asm("mapa.shared::cluster.u32 %0, %1, %2;" : "=r"(pbase[q]) : "r"(sbase), "r"(q));

    CLUSTER_BARRIER();   // mbar init + memB zero visible cluster-wide

    // elementwise role: one cell (bb, ce) per thread
    const int ce = tid & 63;
    const int bb = tid >> 6;                   // batch 0..7
    const int gh = r * 64 + ce;                // global hidden col
    const int src = w >> 1;                    // the ONLY source rank this warp's k-range needs
    const unsigned my_mbar_b0 = mbar_base + (unsigned)(src * 8);
    const unsigned my_mbar_b1 = mbar_base + (unsigned)(64 + src * 8);

    float cnt = 0.f;

    for (int t = 0; t < S_LEN; t++) {
        const int cb = t & 1, nb = cb ^ 1;

        // prefetch T/G (consumed after GEMM)
        const size_t row = ((size_t)t * B_SZ + b0 + bb) * H_SZ + gh;
        const float Tv = g_T[row], Gv = g_G[row];

        // ---- per-warp wait: only my source slice of buffer cb must have landed ----
        if (t > 0) {
            const unsigned ph = (unsigned)(((t - 1) >> 1) & 1);
            const unsigned mb = cb ? my_mbar_b1 : my_mbar_b0;
            asm volatile(
                "{\n\t"
                ".reg .pred P;\n\t"
                "W_%=:\n\t"
                "mbarrier.try_wait.parity.acquire.cta.shared::cta.b64 P, [%0], %1, 0x989680;\n\t"
                "@P bra D_%=;\n\t"
                "bra W_%=;\n\t"
                "D_%=:\n\t"
                "}"
                :: "r"(mb), "r"(ph) : "memory");
        }

        // ---- GEMM: out[b][c] = sum_k memB[cb][k][b] * W[k][c]  (FFMA2, weights in regs) ----
        ull pa[4], pb[4];
#pragma unroll
        for (int j = 0; j < 4; j++) { pa[j] = 0ull; pb[j] = 0ull; }

        const float* mp = memB + cb * 4096 + k0 * 8;
#pragma unroll
        for (int kk = 0; kk < 32; kk++) {
            const ulonglong2 m01 = *(const ulonglong2*)(mp + kk * 8);      // (b0,b1),(b2,b3)
            const ulonglong2 m23 = *(const ulonglong2*)(mp + kk * 8 + 4);  // (b4,b5),(b6,b7)
            const ull w0d = dup2(wreg[2 * kk]);
            const ull w1d = dup2(wreg[2 * kk + 1]);
            pa[0] = ffma2(m01.x, w0d, pa[0]);
            pa[1] = ffma2(m01.y, w0d, pa[1]);
            pa[2] = ffma2(m23.x, w0d, pa[2]);
            pa[3] = ffma2(m23.y, w0d, pa[3]);
            pb[0] = ffma2(m01.x, w1d, pb[0]);
            pb[1] = ffma2(m01.y, w1d, pb[1]);
            pb[2] = ffma2(m23.x, w1d, pb[2]);
            pb[3] = ffma2(m23.y, w1d, pb[3]);
        }
        // warp partials: part[w][b*64 + 2*lane .. +1]  (same layout/values as scalar version)
#pragma unroll
        for (int j = 0; j < 4; j++) {
            const float2 fa = unpack2(pa[j]);   // (acc_a[2j], acc_a[2j+1])
            const float2 fb = unpack2(pb[j]);   // (acc_b[2j], acc_b[2j+1])
            *(float2*)&part[w * 512 + (2 * j)     * 64 + 2 * lane] = make_float2(fa.x, fb.x);
            *(float2*)&part[w * 512 + (2 * j + 1) * 64 + 2 * lane] = make_float2(fa.y, fb.y);
        }
        __syncthreads();

        // ---- reduce 16 warp partials + elementwise update for cell (bb, ce) ----
        float s = 0.f;
#pragma unroll
        for (int ww = 0; ww < 16; ww++)
            s += part[ww * 512 + bb * 64 + ce];
        const float l = Tv + s;
        float beta = 1.f / (1.f + expf(-l));
        beta = fminf(fmaxf(beta, 0.01f), 0.99f);
        const float mo = memB[cb * 4096 + gh * 8 + bb];
        float mn = fmaf(beta, mo, Gv);
        const float sp = ((mn - 1.0f) > 0.0f) ? 1.f : 0.f;
        mn -= sp;
        cnt += sp;

        if (t < S_LEN - 1) {
            // write my slice into my own next buffer
            memB[nb * 4096 + gh * 8 + bb] = mn;
            __syncthreads();   // slice fully written; all GEMM reads of memB[cb] done too

            if (tid == 0) {
                asm volatile("fence.proxy.async;" ::: "memory");
                // arm my 8 per-source barriers for buffer nb
#pragma unroll
                for (int q = 0; q < 8; q++) {
                    const unsigned mb = mbar_base + (unsigned)((nb * 8 + q) * 8);
                    if (q == r) {
                        asm volatile("mbarrier.arrive.shared.b64 _, [%0];"
                                     :: "r"(mb) : "memory");
                    } else {
                        asm volatile("mbarrier.arrive.expect_tx.shared.b64 _, [%0], %1;"
                                     :: "r"(mb), "r"(2048) : "memory");
                    }
                }
                // send my 2KB slice to the 7 peers; complete THEIR mbar[nb][r]
                const unsigned srcaddr = sbase + MEMB_OFF + (unsigned)(nb * 16384 + r * 2048);
                const unsigned doff = MEMB_OFF + (unsigned)(nb * 16384 + r * 2048);
                const unsigned moff = MBAR_OFF + (unsigned)((nb * 8 + r) * 8);
#pragma unroll
                for (int i = 1; i < 8; i++) {
                    const int q = (r + i) & 7;
                    asm volatile(
                        "cp.async.bulk.shared::cluster.shared::cta.mbarrier::complete_tx::bytes"
                        " [%0], [%1], %2, [%3];"
                        :: "r"(pbase[q] + doff), "r"(srcaddr), "r"(2048), "r"(pbase[q] + moff)
                        : "memory");
                }
            }
            // NO cluster-wide wait here: each warp waits on its own slice next step.
        } else {
            // final step: publish my value straight to gmem for the readout
            asm volatile("st.global.cg.f32 [%0], %1;"
                         :: "l"(g_buf + (size_t)cl * 4096 + gh * 8 + bb), "f"(mn) : "memory");
        }
    }

    // spike-count reduction (512 threads)
    __syncthreads();
    part[tid] = cnt;
    __syncthreads();
    if (tid < 256) part[tid] += part[tid + 256];
    __syncthreads();
    if (tid < 128) part[tid] += part[tid + 128];
    __syncthreads();
    if (tid < 64) part[tid] += part[tid + 64];
    __syncthreads();
    if (tid < 32) {
        float v = part[tid] + part[tid + 32];
#pragma unroll
        for (int o = 16; o > 0; o >>= 1) v += __shfl_down_sync(0xffffffffu, v, o);
        if (tid == 0) atomicAdd(&g_cnt, (int)(v + 0.5f));
    }
    CLUSTER_BARRIER();   // no CTA exits while peers' copies may still target its smem
}

// ---------------- Phase 3: readout GEMM + sparsity ----------------
// final mem: mem[b][h] = g_buf[(b>>3)*4096 + h*8 + (b&7)]
__global__ void readout_kernel(const float* __restrict__ Wro, const float* __restrict__ bro,
                               float* __restrict__ out, int out_size)
{
    __shared__ float mrow[512];
    const int row = blockIdx.x;
    const int tid = threadIdx.x;   // 128
    const float* src = g_buf + (size_t)(row >> 3) * 4096 + (row & 7);
    for (int i = tid; i < 512; i += 128) mrow[i] = src[i * 8];
    __syncthreads();
    float acc = bro[tid];
#pragma unroll 8
    for (int k = 0; k < 512; k++)
        acc = fmaf(mrow[k], Wro[(size_t)k * 128 + tid], acc);
    out[(size_t)row * 128 + tid] = acc;
    if (row == 0 && tid == 0 && out_size > B_SZ * C_OUT) {
        out[B_SZ * C_OUT] = 1.0f - (float)g_cnt / (float)((size_t)S_LEN * B_SZ * H_SZ);
    }
}

// ---------------- launch ----------------
extern "C" void kernel_launch(void* const* d_in, const int* in_sizes, int n_in,
                              void* d_out, int out_size)
{
    const float* x    = (const float*)d_in[0];
    const float* Win  = (const float*)d_in[1];
    const float* bin  = (const float*)d_in[2];
    const float* Wtau = (const float*)d_in[3];
    const float* btl  = (const float*)d_in[4];
    const float* bt   = (const float*)d_in[5];
    const float* Wro  = (const float*)d_in[6];
    const float* bro  = (const float*)d_in[7];

    init_kernel<<<1, 1>>>();

    dim3 g1(8, 1024);   // n-tiles x m-tiles
    phase1_kernel<<<g1, 256>>>(x, Win, bin, Wtau, btl, bt);

    cudaFuncSetAttribute(recurrent_kernel, cudaFuncAttributeMaxDynamicSharedMemorySize, REC_SMEM);
    recurrent_kernel<<<128, 512, REC_SMEM>>>(Wtau);

    readout_kernel<<<B_SZ, C_OUT>>>(Wro, bro, (float*)d_out, out_size);
}